// round 14
// baseline (speedup 1.0000x reference)
#include <cuda_runtime.h>

#define DD 64
#define NMAX 100352
#define EMAX 1703936
#define ALPHA 0.2f

// Scratch (static device arrays; no allocation anywhere)
__device__ float2 g_src[NMAX];       // per-node {s_src_h0, s_src_h1}
__device__ float2 g_dst[NMAX];       // per-node {s_dst_h0, s_dst_h1}
__device__ int    g_cnt[NMAX];       // per-row edge counts
__device__ int    g_off[NMAX + 1];   // row segment start offsets (CSR)
__device__ int    g_woff[NMAX];      // working offsets for scatter
__device__ int    g_scol[EMAX];      // col indices grouped by row
__device__ float2 g_sev[EMAX];       // per-edge {e_h0, e_h1}, grouped by row

// Per-node dual-head src/dst dot products + zero counts.
__global__ void k_prep(const float* __restrict__ x, const float* __restrict__ W,
                       const float* __restrict__ a, int n) {
    __shared__ float2 cs[DD];  // {W0[k]*a0[k],    W1[k]*a1[k]}
    __shared__ float2 cd[DD];  // {W0[k]*a0[D+k],  W1[k]*a1[D+k]}
    for (int k = threadIdx.x; k < DD; k += blockDim.x) {
        float w0 = W[k], w1 = W[DD + k];
        cs[k] = make_float2(w0 * a[k],      w1 * a[2 * DD + k]);
        cd[k] = make_float2(w0 * a[DD + k], w1 * a[3 * DD + k]);
    }
    __syncthreads();
    int i = blockIdx.x * blockDim.x + threadIdx.x;
    if (i >= n) return;
    g_cnt[i] = 0;
    const float4* xv = (const float4*)(x + (size_t)i * DD);
    float s0 = 0.f, s1 = 0.f, d0 = 0.f, d1 = 0.f;
#pragma unroll
    for (int k4 = 0; k4 < DD / 4; k4++) {
        float4 v = xv[k4];
        float vv[4] = {v.x, v.y, v.z, v.w};
#pragma unroll
        for (int j = 0; j < 4; j++) {
            float2 c1 = cs[4 * k4 + j];
            float2 c2 = cd[4 * k4 + j];
            s0 += vv[j] * c1.x; s1 += vv[j] * c1.y;
            d0 += vv[j] * c2.x; d1 += vv[j] * c2.y;
        }
    }
    g_src[i] = make_float2(s0, s1);
    g_dst[i] = make_float2(d0, d1);
}

// Histogram of row degrees.
__global__ void k_hist(const int* __restrict__ ei, int E) {
    int e = blockIdx.x * blockDim.x + threadIdx.x;
    if (e >= E) return;
    atomicAdd(&g_cnt[__ldg(ei + e)], 1);
}

// Single-block exclusive scan of g_cnt -> g_off (and g_woff copy).
__global__ void k_scan(int n, int E) {
    __shared__ int sums[1024];
    int t = threadIdx.x;
    int chunk = (n + 1023) >> 10;
    int lo = t * chunk; if (lo > n) lo = n;
    int hi = lo + chunk; if (hi > n) hi = n;
    int s = 0;
    for (int i = lo; i < hi; i++) s += g_cnt[i];
    sums[t] = s;
    __syncthreads();
    for (int d = 1; d < 1024; d <<= 1) {
        int u = (t >= d) ? sums[t - d] : 0;
        __syncthreads();
        sums[t] += u;
        __syncthreads();
    }
    int run = sums[t] - s;  // exclusive prefix of this thread's chunk
    for (int i = lo; i < hi; i++) {
        int c = g_cnt[i];
        g_off[i] = run;
        g_woff[i] = run;
        run += c;
    }
    if (t == 0) g_off[n] = E;
}

// Scatter pass, now fused with e-value computation: reads the edge, computes
// e0/e1 = exp(leaky_relu(s_src[r] + s_dst[c])) here (fully parallel across
// edges — MUFU spread over all threads instead of 1/16 leader lanes), and
// stores {col, e0, e1} in row-grouped order. This removes the dependent
// g_scol[j] -> g_dst[c] pointer-chase from k_row's leader entirely.
__global__ void k_scatter(const int* __restrict__ ei, int E) {
    int e = blockIdx.x * blockDim.x + threadIdx.x;
    if (e >= E) return;
    int r = __ldg(ei + e);
    int c = __ldg(ei + E + e);
    float2 ss = __ldg(&g_src[r]);
    float2 sd = __ldg(&g_dst[c]);
    float sc0 = ss.x + sd.x;
    float sc1 = ss.y + sd.y;
    sc0 = sc0 > 0.f ? sc0 : ALPHA * sc0;
    sc1 = sc1 > 0.f ? sc1 : ALPHA * sc1;
    float e0 = __expf(sc0);
    float e1 = __expf(sc1);
    int pos = atomicAdd(&g_woff[r], 1);
    g_scol[pos] = c;
    g_sev[pos] = make_float2(e0, e1);
}

// Fused row pass: one 16-lane group per row. Leader lane streams the row's
// {col, e-value} lists — two independent contiguous loads per edge, software-
// pipelined (no dependent chase) — accumulates rowsums in registers and
// broadcasts {c, e0, e1}. All lanes gather x[c] (one float4 each) and keep
// two head accumulators in registers. Epilogue folds normalization +
// head-mean into one STG.128 per lane — no atomics, no out zero-init.
// Shuffle masks are per half-warp; trip counts are uniform within each
// 16-lane group (start/end broadcast before the loop).
__global__ void k_row(const float* __restrict__ x, float* __restrict__ out, int n) {
    int gid = blockIdx.x * blockDim.x + threadIdx.x;
    int row = gid >> 4;
    int l = gid & 15;
    bool valid = row < n;
    int rowc = valid ? row : 0;
    unsigned m = 0xFFFFu << (threadIdx.x & 16);
    int start = 0, end = 0;
    if (l == 0) {
        start = g_off[rowc];
        end = g_off[rowc + 1];
    }
    start = __shfl_sync(m, start, 0, 16);
    end   = __shfl_sync(m, end, 0, 16);

    float4 a0 = make_float4(0.f, 0.f, 0.f, 0.f);
    float4 a1 = make_float4(0.f, 0.f, 0.f, 0.f);
    float rs0 = 0.f, rs1 = 0.f;          // leader-only
    int c_p = 0;
    float2 ev_p = make_float2(0.f, 0.f);
    if (l == 0 && start < end) {         // prime the pipeline
        c_p = __ldg(&g_scol[start]);
        ev_p = __ldg(&g_sev[start]);
    }
    for (int j = start; j < end; j++) {
        int c = c_p;
        float2 ev = ev_p;
        if (l == 0 && j + 1 < end) {     // prefetch next edge (independent loads)
            c_p = __ldg(&g_scol[j + 1]);
            ev_p = __ldg(&g_sev[j + 1]);
        }
        float e0 = 0.f, e1 = 0.f;
        if (l == 0) {
            e0 = ev.x; e1 = ev.y;
            rs0 += e0; rs1 += e1;
        }
        c  = __shfl_sync(m, c, 0, 16);
        e0 = __shfl_sync(m, e0, 0, 16);
        e1 = __shfl_sync(m, e1, 0, 16);
        float4 v = __ldg((const float4*)x + (size_t)c * 16 + l);
        a0.x += e0 * v.x; a0.y += e0 * v.y; a0.z += e0 * v.z; a0.w += e0 * v.w;
        a1.x += e1 * v.x; a1.y += e1 * v.y; a1.z += e1 * v.z; a1.w += e1 * v.w;
    }
    float w0 = 0.f, w1 = 0.f;
    if (l == 0) {
        w0 = rs0 > 0.f ? __fdividef(0.5f, rs0) : 0.f;
        w1 = rs1 > 0.f ? __fdividef(0.5f, rs1) : 0.f;
    }
    w0 = __shfl_sync(m, w0, 0, 16);
    w1 = __shfl_sync(m, w1, 0, 16);
    if (valid) {
        float4 o;
        o.x = w0 * a0.x + w1 * a1.x;
        o.y = w0 * a0.y + w1 * a1.y;
        o.z = w0 * a0.z + w1 * a1.z;
        o.w = w0 * a0.w + w1 * a1.w;
        ((float4*)out)[(size_t)row * 16 + l] = o;
    }
}

extern "C" void kernel_launch(void* const* d_in, const int* in_sizes, int n_in,
                              void* d_out, int out_size) {
    const float* x  = (const float*)d_in[0];   // [N, 64]
    const int*   ei = (const int*)d_in[1];     // [2, E]
    const float* W  = (const float*)d_in[2];   // [2, 64]
    const float* a  = (const float*)d_in[3];   // [2, 128]
    float* out = (float*)d_out;                // [N, 64]

    int n = in_sizes[0] / DD;
    int E = in_sizes[1] / 2;
    if (n > NMAX) n = NMAX;
    if (E > EMAX) E = EMAX;

    k_prep<<<(n + 255) / 256, 256>>>(x, W, a, n);
    k_hist<<<(E + 255) / 256, 256>>>(ei, E);
    k_scan<<<1, 1024>>>(n, E);
    k_scatter<<<(E + 255) / 256, 256>>>(ei, E);
    long long t = (long long)n * 16;
    k_row<<<(int)((t + 255) / 256), 256>>>(x, out, n);
}